// round 3
// baseline (speedup 1.0000x reference)
#include <cuda_runtime.h>

// Controlled 2-qubit gate on a 2^26 fp32 statevector.
// Targets: qubits 0,1 -> bits 25,24. Control: qubit 2 -> bit 23.
// Granule index i in [0, 2^22) per t-stream (float4 = 4 elems); control bit
// = bit 21 of i. Each thread handles 2 granules with the SAME control bit:
//   g0 = (tid>>20)<<21 | (tid & 0xFFFFF),  g1 = g0 + 2^20
// -> 8 independent front-batched LDG.128, warp-uniform branch, default cache.

#define QGRP (1 << 22)   // float4 granules per t-stream

__global__ void __launch_bounds__(256) gate_kernel(
    const float4* __restrict__ in4,
    const float*  __restrict__ m,
    float4*       __restrict__ out4)
{
    const int tid = blockIdx.x * blockDim.x + threadIdx.x;   // 0 .. 2^21-1
    const int chunk  = tid >> 20;                            // control bit
    const int within = tid & ((1 << 20) - 1);
    const int g0 = (chunk << 21) | within;
    const int g1 = g0 + (1 << 20);

    // Front-batch all 8 independent loads.
    float4 a0 = in4[g0];
    float4 a1 = in4[g0 + QGRP];
    float4 a2 = in4[g0 + 2 * QGRP];
    float4 a3 = in4[g0 + 3 * QGRP];
    float4 b0 = in4[g1];
    float4 b1 = in4[g1 + QGRP];
    float4 b2 = in4[g1 + 2 * QGRP];
    float4 b3 = in4[g1 + 3 * QGRP];

    if (chunk) {  // control on: apply 4x4 gate to both granule groups
        const float m00 = __ldg(m + 0),  m01 = __ldg(m + 1),  m02 = __ldg(m + 2),  m03 = __ldg(m + 3);
        const float m10 = __ldg(m + 4),  m11 = __ldg(m + 5),  m12 = __ldg(m + 6),  m13 = __ldg(m + 7);
        const float m20 = __ldg(m + 8),  m21 = __ldg(m + 9),  m22 = __ldg(m + 10), m23 = __ldg(m + 11);
        const float m30 = __ldg(m + 12), m31 = __ldg(m + 13), m32 = __ldg(m + 14), m33 = __ldg(m + 15);

        float4 y0, y1, y2, y3;
        #define APPLY(p0,p1,p2,p3,c) \
            y0.c = m00 * p0.c + m01 * p1.c + m02 * p2.c + m03 * p3.c; \
            y1.c = m10 * p0.c + m11 * p1.c + m12 * p2.c + m13 * p3.c; \
            y2.c = m20 * p0.c + m21 * p1.c + m22 * p2.c + m23 * p3.c; \
            y3.c = m30 * p0.c + m31 * p1.c + m32 * p2.c + m33 * p3.c;

        APPLY(a0, a1, a2, a3, x); APPLY(a0, a1, a2, a3, y);
        APPLY(a0, a1, a2, a3, z); APPLY(a0, a1, a2, a3, w);
        a0 = y0; a1 = y1; a2 = y2; a3 = y3;

        APPLY(b0, b1, b2, b3, x); APPLY(b0, b1, b2, b3, y);
        APPLY(b0, b1, b2, b3, z); APPLY(b0, b1, b2, b3, w);
        b0 = y0; b1 = y1; b2 = y2; b3 = y3;
        #undef APPLY
    }

    out4[g0]            = a0;
    out4[g0 + QGRP]     = a1;
    out4[g0 + 2 * QGRP] = a2;
    out4[g0 + 3 * QGRP] = a3;
    out4[g1]            = b0;
    out4[g1 + QGRP]     = b1;
    out4[g1 + 2 * QGRP] = b2;
    out4[g1 + 3 * QGRP] = b3;
}

extern "C" void kernel_launch(void* const* d_in, const int* in_sizes, int n_in,
                              void* d_out, int out_size)
{
    const float* x = (const float*)d_in[0];   // 2^26 floats
    const float* m = (const float*)d_in[1];   // 16 floats (4x4 row-major)
    float* out = (float*)d_out;               // 2^26 floats

    const int n_threads = 1 << 21;            // 2 granules x 4 streams each
    const int block = 256;
    const int grid = n_threads / block;       // 8192
    gate_kernel<<<grid, block>>>((const float4*)x, m, (float4*)out);
}

// round 4
// speedup vs baseline: 1.0008x; 1.0008x over previous
#include <cuda_runtime.h>

// Controlled 2-qubit gate on a 2^26 fp32 statevector.
// Targets: qubits 0,1 -> bits 25,24 of the flat index. Control: qubit 2 -> bit 23.
// R1 structure (best so far): 1 granule x 4 streams per thread, warp-uniform
// control branch, default-cache loads. Single change: evict-first (.cs) STORES
// so the write stream doesn't pollute L2 against the read fills.

#define QGRP (1 << 22)   // float4-granule count per t-stream (2^24 floats / 4)

__global__ void __launch_bounds__(256) gate_kernel(
    const float4* __restrict__ in4,
    const float*  __restrict__ m,
    float4*       __restrict__ out4)
{
    const int tid = blockIdx.x * blockDim.x + threadIdx.x;  // 0 .. 2^22-1

    float4 a0 = in4[tid];
    float4 a1 = in4[tid + QGRP];
    float4 a2 = in4[tid + 2 * QGRP];
    float4 a3 = in4[tid + 3 * QGRP];

    // control bit: bit 23 of element base (= tid*4) -> bit 21 of tid.
    // Uniform across 2^21 consecutive tids -> no warp divergence.
    if ((tid >> 21) & 1) {
        const float m00 = __ldg(m + 0),  m01 = __ldg(m + 1),  m02 = __ldg(m + 2),  m03 = __ldg(m + 3);
        const float m10 = __ldg(m + 4),  m11 = __ldg(m + 5),  m12 = __ldg(m + 6),  m13 = __ldg(m + 7);
        const float m20 = __ldg(m + 8),  m21 = __ldg(m + 9),  m22 = __ldg(m + 10), m23 = __ldg(m + 11);
        const float m30 = __ldg(m + 12), m31 = __ldg(m + 13), m32 = __ldg(m + 14), m33 = __ldg(m + 15);

        float4 y0, y1, y2, y3;
        #define APPLY(c) \
            y0.c = m00 * a0.c + m01 * a1.c + m02 * a2.c + m03 * a3.c; \
            y1.c = m10 * a0.c + m11 * a1.c + m12 * a2.c + m13 * a3.c; \
            y2.c = m20 * a0.c + m21 * a1.c + m22 * a2.c + m23 * a3.c; \
            y3.c = m30 * a0.c + m31 * a1.c + m32 * a2.c + m33 * a3.c;
        APPLY(x); APPLY(y); APPLY(z); APPLY(w);
        #undef APPLY

        a0 = y0; a1 = y1; a2 = y2; a3 = y3;
    }

    __stcs(out4 + tid,            a0);
    __stcs(out4 + tid + QGRP,     a1);
    __stcs(out4 + tid + 2 * QGRP, a2);
    __stcs(out4 + tid + 3 * QGRP, a3);
}

extern "C" void kernel_launch(void* const* d_in, const int* in_sizes, int n_in,
                              void* d_out, int out_size)
{
    const float* x = (const float*)d_in[0];   // 2^26 floats
    const float* m = (const float*)d_in[1];   // 16 floats (4x4 row-major)
    float* out = (float*)d_out;               // 2^26 floats

    const int n_threads = QGRP;               // 2^22 float4 groups
    const int block = 256;
    const int grid = n_threads / block;       // 16384
    gate_kernel<<<grid, block>>>((const float4*)x, m, (float4*)out);
}

// round 5
// speedup vs baseline: 1.0039x; 1.0031x over previous
#include <cuda_runtime.h>

// Controlled 2-qubit gate on a 2^26 fp32 statevector.
// Targets: qubits 0,1 -> bits 25,24 of the flat index. Control: qubit 2 -> bit 23.
// 256-bit global loads/stores (sm_100+ LDG.E.256): each thread handles 8
// consecutive floats in each of the 4 t-streams. Element base = tid*8, so the
// control bit (bit 23) is bit 20 of tid -> warp-uniform over 2^20 threads.

#define STREAM_ELEMS (1 << 24)   // floats per t-stream

__device__ __forceinline__ void ldg256(const float* p, float* v) {
    asm volatile("ld.global.v8.f32 {%0,%1,%2,%3,%4,%5,%6,%7}, [%8];"
                 : "=f"(v[0]), "=f"(v[1]), "=f"(v[2]), "=f"(v[3]),
                   "=f"(v[4]), "=f"(v[5]), "=f"(v[6]), "=f"(v[7])
                 : "l"(p));
}

__device__ __forceinline__ void stg256(float* p, const float* v) {
    asm volatile("st.global.cs.v8.f32 [%0], {%1,%2,%3,%4,%5,%6,%7,%8};"
                 :: "l"(p),
                    "f"(v[0]), "f"(v[1]), "f"(v[2]), "f"(v[3]),
                    "f"(v[4]), "f"(v[5]), "f"(v[6]), "f"(v[7])
                 : "memory");
}

__global__ void __launch_bounds__(256) gate_kernel(
    const float* __restrict__ in,
    const float* __restrict__ m,
    float*       __restrict__ out)
{
    const int tid = blockIdx.x * blockDim.x + threadIdx.x;  // 0 .. 2^21-1
    const long base = (long)tid * 8;

    float a0[8], a1[8], a2[8], a3[8];
    ldg256(in + base,                    a0);
    ldg256(in + base + STREAM_ELEMS,     a1);
    ldg256(in + base + 2 * STREAM_ELEMS, a2);
    ldg256(in + base + 3 * STREAM_ELEMS, a3);

    // control bit: bit 23 of element base (= tid*8) -> bit 20 of tid.
    if ((tid >> 20) & 1) {
        const float m00 = __ldg(m + 0),  m01 = __ldg(m + 1),  m02 = __ldg(m + 2),  m03 = __ldg(m + 3);
        const float m10 = __ldg(m + 4),  m11 = __ldg(m + 5),  m12 = __ldg(m + 6),  m13 = __ldg(m + 7);
        const float m20 = __ldg(m + 8),  m21 = __ldg(m + 9),  m22 = __ldg(m + 10), m23 = __ldg(m + 11);
        const float m30 = __ldg(m + 12), m31 = __ldg(m + 13), m32 = __ldg(m + 14), m33 = __ldg(m + 15);

        #pragma unroll
        for (int j = 0; j < 8; j++) {
            const float v0 = a0[j], v1 = a1[j], v2 = a2[j], v3 = a3[j];
            a0[j] = m00 * v0 + m01 * v1 + m02 * v2 + m03 * v3;
            a1[j] = m10 * v0 + m11 * v1 + m12 * v2 + m13 * v3;
            a2[j] = m20 * v0 + m21 * v1 + m22 * v2 + m23 * v3;
            a3[j] = m30 * v0 + m31 * v1 + m32 * v2 + m33 * v3;
        }
    }

    stg256(out + base,                    a0);
    stg256(out + base + STREAM_ELEMS,     a1);
    stg256(out + base + 2 * STREAM_ELEMS, a2);
    stg256(out + base + 3 * STREAM_ELEMS, a3);
}

extern "C" void kernel_launch(void* const* d_in, const int* in_sizes, int n_in,
                              void* d_out, int out_size)
{
    const float* x = (const float*)d_in[0];   // 2^26 floats
    const float* m = (const float*)d_in[1];   // 16 floats (4x4 row-major)
    float* out = (float*)d_out;               // 2^26 floats

    const int n_threads = STREAM_ELEMS / 8;   // 2^21
    const int block = 256;
    const int grid = n_threads / block;       // 8192
    gate_kernel<<<grid, block>>>(x, m, out);
}